// round 9
// baseline (speedup 1.0000x reference)
#include <cuda_runtime.h>

// POLLU RHS: dy[b, 0:20] = S @ flux(b), flux_r = k_r * C[a_r,b] * C[b_r,b]
// R3: smem staging with stride 20 == output layout. Key facts:
//   - STS.128 at 80B stride: phase of 8 lanes starts at banks (20t)%32 =
//     {0,20,8,28,16,4,24,12}; each 4-bank span tiles all 32 banks -> conflict-free.
//   - col*20 + 4*(f%5) == 4f: smem is the gmem output tile verbatim, so the
//     epilogue is a sequential float4 copy (no div/mod, conflict-free LDS.128).
//   - smem 20.5KB -> 8 blocks/SM (warp-limited occupancy cap).

constexpr int TPB = 256;

__global__ void __launch_bounds__(TPB) pollu_kernel(
    const float* __restrict__ C,   // [20, B]
    const float* __restrict__ k,   // [25]
    float* __restrict__ out,       // [B, 20]
    int B)
{
    __shared__ float sm[TPB * 20];  // 20480 B, identical layout to out[base:base+TPB, 0:20]

    const int tid  = threadIdx.x;
    const int base = blockIdx.x * TPB;
    const int b    = base + tid;

    if (b < B) {
        // Coalesced, streaming (use-once) row loads. Rows 7,11,14,17 unused.
        float c0  = __ldcs(&C[(size_t)0  * B + b]);
        float c1  = __ldcs(&C[(size_t)1  * B + b]);
        float c2  = __ldcs(&C[(size_t)2  * B + b]);
        float c3  = __ldcs(&C[(size_t)3  * B + b]);
        float c4  = __ldcs(&C[(size_t)4  * B + b]);
        float c5  = __ldcs(&C[(size_t)5  * B + b]);
        float c6  = __ldcs(&C[(size_t)6  * B + b]);
        float c8  = __ldcs(&C[(size_t)8  * B + b]);
        float c9  = __ldcs(&C[(size_t)9  * B + b]);
        float c10 = __ldcs(&C[(size_t)10 * B + b]);
        float c12 = __ldcs(&C[(size_t)12 * B + b]);
        float c13 = __ldcs(&C[(size_t)13 * B + b]);
        float c15 = __ldcs(&C[(size_t)15 * B + b]);
        float c16 = __ldcs(&C[(size_t)16 * B + b]);
        float c18 = __ldcs(&C[(size_t)18 * B + b]);
        float c19 = __ldcs(&C[(size_t)19 * B + b]);

        float r1  = __ldg(&k[0])  * c0;
        float r2  = __ldg(&k[1])  * c1  * c3;
        float r3  = __ldg(&k[2])  * c4  * c1;
        float r4  = __ldg(&k[3])  * c6;
        float r5  = __ldg(&k[4])  * c6;
        float r6  = __ldg(&k[5])  * c6  * c5;
        float r7  = __ldg(&k[6])  * c8;
        float r8  = __ldg(&k[7])  * c8  * c5;
        float r9  = __ldg(&k[8])  * c10 * c1;
        float r10 = __ldg(&k[9])  * c10 * c0;
        float r11 = __ldg(&k[10]) * c12;
        float r12 = __ldg(&k[11]) * c9  * c1;
        float r13 = __ldg(&k[12]) * c13;
        float r14 = __ldg(&k[13]) * c0  * c5;
        float r15 = __ldg(&k[14]) * c2;
        float r16 = __ldg(&k[15]) * c3;
        float r17 = __ldg(&k[16]) * c3;
        float r18 = __ldg(&k[17]) * c15;
        float r19 = __ldg(&k[18]) * c15;
        float r20 = __ldg(&k[19]) * c16 * c5;
        float r21 = __ldg(&k[20]) * c18;
        float r22 = __ldg(&k[21]) * c18;
        float r23 = __ldg(&k[22]) * c0  * c3;
        float r24 = __ldg(&k[23]) * c18 * c0;
        float r25 = __ldg(&k[24]) * c19;

        float dy0  = -r1 - r10 - r14 - r23 - r24 + r2 + r3 + r9 + r11 + r12 + r22 + r25;
        float dy1  = -r2 - r3 - r9 - r12 + r1 + r21;
        float dy2  = -r15 + r1 + r17 + r19 + r22;
        float dy3  = -r2 - r16 - r17 - r23 + r15;
        float dy4  = -r3 + 2.0f * r4 + r6 + r7 + r13 + r20;
        float dy5  = -r6 - r8 - r14 - r20 + r3 + 2.0f * r18;
        float dy6  = -r4 - r5 - r6 + r13;
        float dy7  =  r4 + r5 + r6 + r7;
        float dy8  = -r7 - r8;
        float dy9  = -r12 + r7 + r9;
        float dy10 = -r9 - r10 + r8 + r11;
        float dy11 =  r9;
        float dy12 = -r11 + r10;
        float dy13 = -r13 + r12;
        float dy14 =  r14;
        float dy15 = -r18 - r19 + r16;
        float dy16 = -r20;
        float dy17 =  r20;
        float dy18 = -r21 - r22 - r24 + r23 + r25;
        float dy19 = -r25 + r24;

        // Stage to smem at 80B column stride (conflict-free STS.128).
        float4* s4 = reinterpret_cast<float4*>(&sm[tid * 20]);
        s4[0] = make_float4(dy0,  dy1,  dy2,  dy3);
        s4[1] = make_float4(dy4,  dy5,  dy6,  dy7);
        s4[2] = make_float4(dy8,  dy9,  dy10, dy11);
        s4[3] = make_float4(dy12, dy13, dy14, dy15);
        s4[4] = make_float4(dy16, dy17, dy18, dy19);
    }
    __syncthreads();

    // Epilogue: smem layout == gmem layout; straight sequential float4 copy.
    int ncols = B - base;
    if (ncols > TPB) ncols = TPB;
    const int nf4 = ncols * 5;

    const float4* s4 = reinterpret_cast<const float4*>(sm);
    float4* o4 = reinterpret_cast<float4*>(out + (size_t)base * 20);
    #pragma unroll
    for (int i = 0; i < 5; i++) {
        int f = tid + i * TPB;
        if (f < nf4) {
            __stcs(&o4[f], s4[f]);
        }
    }
}

extern "C" void kernel_launch(void* const* d_in, const int* in_sizes, int n_in,
                              void* d_out, int out_size) {
    // metadata order: t [1], conc_in [20*B], k [25]
    const float* conc = (const float*)d_in[1];
    const float* k    = (const float*)d_in[2];
    float* out        = (float*)d_out;
    int B = in_sizes[1] / 20;

    int blocks = (B + TPB - 1) / TPB;
    pollu_kernel<<<blocks, TPB>>>(conc, k, out, B);
}